// round 13
// baseline (speedup 1.0000x reference)
#include <cuda_runtime.h>
#include <cstdint>

#define EMB 128
#define MAX_USERS 65536
#define MAX_GROUPS 4096

// scratch (allocation-free rule: __device__ globals)
__device__ float g_per_user[(size_t)MAX_USERS * EMB];   // 32 MB, L2-resident
__device__ int   g_u_off[MAX_USERS + 1];
__device__ int   g_g_off[MAX_GROUPS + 1];

// ---------------------------------------------------------------------------
// Prologue: O(n) adjacency scatter, 32 keys per thread (8 x int4, MLP=8).
//   u_off[u] = lower_bound(buid, u),  g_off[g] = lower_bound(ugid, g)
// ---------------------------------------------------------------------------
__device__ __forceinline__ void scatter32(const int* __restrict__ keys, int n,
                                          int* __restrict__ off, int max_key,
                                          int slot)
{
    const int base = slot * 32;
    if (base >= n) return;

    if (base + 32 <= n) {
        int k[32];
#pragma unroll
        for (int q = 0; q < 8; q++) {
            int4 v = *reinterpret_cast<const int4*>(keys + base + q * 4);
            k[q * 4 + 0] = v.x; k[q * 4 + 1] = v.y;
            k[q * 4 + 2] = v.z; k[q * 4 + 3] = v.w;
        }
        int prev = (base == 0) ? -1 : __ldg(keys + base - 1);
#pragma unroll
        for (int t = 0; t < 32; t++) {
            for (int u = prev + 1; u <= k[t]; u++) off[u] = base + t;
            prev = k[t];
        }
        if (base + 32 == n) {
            for (int u = prev + 1; u <= max_key; u++) off[u] = n;
        }
    } else {
        int prev = (base == 0) ? -1 : __ldg(keys + base - 1);
        for (int j = base; j < n; j++) {
            int cur = __ldg(keys + j);
            for (int u = prev + 1; u <= cur; u++) off[u] = j;
            prev = cur;
        }
        for (int u = prev + 1; u <= max_key; u++) off[u] = n;
    }
}

__global__ void __launch_bounds__(256) offsets_scatter_kernel(
    const int* __restrict__ buid, const int* __restrict__ ugid,
    int n_beh, int n_users, int num_groups)
{
    const int i = blockIdx.x * blockDim.x + threadIdx.x;
    const int n_beh_slots = (n_beh + 31) >> 5;

    if (i < n_beh_slots) {
        scatter32(buid, n_beh, g_u_off, n_users, i);
    } else {
        scatter32(ugid, n_users, g_g_off, num_groups, i - n_beh_slots);
    }
}

// ---------------------------------------------------------------------------
// Kernel 1: one warp per user (65536 independent warps -> perfect balance).
// Offsets precomputed. Unroll x4, 2 accumulators. Scratch stays L2-resident.
// This kernel runs at the LTS throughput cap (~13 TB/s of L2 gather traffic).
// ---------------------------------------------------------------------------
__global__ void __launch_bounds__(256) per_user_kernel(
    const int* __restrict__ user_ids,
    const int* __restrict__ bitem,
    const float* __restrict__ bcnt,
    const float* __restrict__ user_table,
    const float* __restrict__ item_table,
    int n_users)
{
    const int warp = (blockIdx.x * blockDim.x + threadIdx.x) >> 5;
    const int lane = threadIdx.x & 31;
    if (warp >= n_users) return;
    const int u   = warp;
    const int col = lane * 4;

    float4* dst = reinterpret_cast<float4*>(g_per_user + (size_t)u * EMB + col);

    const int uid = __ldg(user_ids + u);
    if (uid == 0) {
        *dst = make_float4(0.f, 0.f, 0.f, 0.f);
        return;
    }

    const int s = g_u_off[u];
    const int e = g_u_off[u + 1];

    float4 a0 = make_float4(0.f, 0.f, 0.f, 0.f);
    float4 a1 = make_float4(0.f, 0.f, 0.f, 0.f);

    int j = s;
    for (; j + 3 < e; j += 4) {
        int   i0 = __ldcs(bitem + j + 0);
        int   i1 = __ldcs(bitem + j + 1);
        int   i2 = __ldcs(bitem + j + 2);
        int   i3 = __ldcs(bitem + j + 3);
        float c0 = __ldcs(bcnt + j + 0);
        float c1 = __ldcs(bcnt + j + 1);
        float c2 = __ldcs(bcnt + j + 2);
        float c3 = __ldcs(bcnt + j + 3);
        float4 v0 = *reinterpret_cast<const float4*>(item_table + (size_t)i0 * EMB + col);
        float4 v1 = *reinterpret_cast<const float4*>(item_table + (size_t)i1 * EMB + col);
        float4 v2 = *reinterpret_cast<const float4*>(item_table + (size_t)i2 * EMB + col);
        float4 v3 = *reinterpret_cast<const float4*>(item_table + (size_t)i3 * EMB + col);
        a0.x += c0 * v0.x; a0.y += c0 * v0.y; a0.z += c0 * v0.z; a0.w += c0 * v0.w;
        a1.x += c1 * v1.x; a1.y += c1 * v1.y; a1.z += c1 * v1.z; a1.w += c1 * v1.w;
        a0.x += c2 * v2.x; a0.y += c2 * v2.y; a0.z += c2 * v2.z; a0.w += c2 * v2.w;
        a1.x += c3 * v3.x; a1.y += c3 * v3.y; a1.z += c3 * v3.z; a1.w += c3 * v3.w;
    }
    for (; j < e; j++) {
        int   i0 = __ldcs(bitem + j);
        float c0 = __ldcs(bcnt + j);
        float4 v0 = *reinterpret_cast<const float4*>(item_table + (size_t)i0 * EMB + col);
        a0.x += c0 * v0.x; a0.y += c0 * v0.y; a0.z += c0 * v0.z; a0.w += c0 * v0.w;
    }

    float4 ue = *reinterpret_cast<const float4*>(user_table + (size_t)uid * EMB + col);
    float4 outv;
    outv.x = (a0.x + a1.x) * ue.x;
    outv.y = (a0.y + a1.y) * ue.y;
    outv.z = (a0.z + a1.z) * ue.z;
    outv.w = (a0.w + a1.w) * ue.w;
    *dst = outv;
}

// ---------------------------------------------------------------------------
// Kernel 2: one 256-thread CTA per group. 32 lanes own float4 column slices,
// 8 user-partitions in parallel (stride 8), fixed-order smem combine.
// Scratch is L2-resident -> L2-bandwidth reads.
// ---------------------------------------------------------------------------
__global__ void __launch_bounds__(256) group_sum_kernel(
    float* __restrict__ out, int num_groups)
{
    const int g    = blockIdx.x;
    const int lane = threadIdx.x & 31;
    const int part = threadIdx.x >> 5;   // 0..7
    const int col  = lane * 4;

    __shared__ float4 s_part[8][32];

    const int s = g_g_off[g];
    const int e = g_g_off[g + 1];

    float4 acc = make_float4(0.f, 0.f, 0.f, 0.f);
    for (int u = s + part; u < e; u += 8) {
        float4 v = *reinterpret_cast<const float4*>(g_per_user + (size_t)u * EMB + col);
        acc.x += v.x; acc.y += v.y; acc.z += v.z; acc.w += v.w;
    }
    s_part[part][lane] = acc;
    __syncthreads();

    if (part == 0) {
        float4 r = make_float4(0.f, 0.f, 0.f, 0.f);
#pragma unroll
        for (int p = 0; p < 8; p++) {
            float4 v = s_part[p][lane];
            r.x += v.x; r.y += v.y; r.z += v.z; r.w += v.w;
        }
        *reinterpret_cast<float4*>(out + (size_t)g * EMB + col) = r;
    }
}

extern "C" void kernel_launch(void* const* d_in, const int* in_sizes, int n_in,
                              void* d_out, int out_size)
{
    const int*   user_ids   = (const int*)  d_in[0];
    const int*   ugid       = (const int*)  d_in[1];
    const int*   bitem      = (const int*)  d_in[2];
    const float* bcnt       = (const float*)d_in[3];
    const int*   buid       = (const int*)  d_in[4];
    const float* user_table = (const float*)d_in[5];
    const float* item_table = (const float*)d_in[6];

    const int n_users    = in_sizes[0];
    const int n_beh      = in_sizes[2];
    const int num_groups = out_size / EMB;

    float* out = (float*)d_out;

    {
        int slots = ((n_beh + 31) >> 5) + ((n_users + 31) >> 5);
        offsets_scatter_kernel<<<(slots + 255) / 256, 256>>>(
            buid, ugid, n_beh, n_users, num_groups);
    }

    {
        const int warps_per_block = 8;
        const int threads = warps_per_block * 32;
        const int blocks = (n_users + warps_per_block - 1) / warps_per_block;
        per_user_kernel<<<blocks, threads>>>(user_ids, bitem, bcnt,
                                             user_table, item_table, n_users);
    }

    group_sum_kernel<<<num_groups, 256>>>(out, num_groups);
}

// round 14
// speedup vs baseline: 1.0225x; 1.0225x over previous
#include <cuda_runtime.h>
#include <cstdint>

#define EMB 128
#define MAX_USERS 65536
#define MAX_GROUPS 4096

// scratch (allocation-free rule: __device__ globals)
__device__ float g_per_user[(size_t)MAX_USERS * EMB];   // 32 MB, L2-resident
__device__ int   g_u_off[MAX_USERS + 1];
__device__ int   g_g_off[MAX_GROUPS + 1];

// ---------------------------------------------------------------------------
// Prologue: O(n) adjacency scatter, 32 keys per thread (8 x int4, MLP=8).
//   u_off[u] = lower_bound(buid, u),  g_off[g] = lower_bound(ugid, g)
// ---------------------------------------------------------------------------
__device__ __forceinline__ void scatter32(const int* __restrict__ keys, int n,
                                          int* __restrict__ off, int max_key,
                                          int slot)
{
    const int base = slot * 32;
    if (base >= n) return;

    if (base + 32 <= n) {
        int k[32];
#pragma unroll
        for (int q = 0; q < 8; q++) {
            int4 v = *reinterpret_cast<const int4*>(keys + base + q * 4);
            k[q * 4 + 0] = v.x; k[q * 4 + 1] = v.y;
            k[q * 4 + 2] = v.z; k[q * 4 + 3] = v.w;
        }
        int prev = (base == 0) ? -1 : __ldg(keys + base - 1);
#pragma unroll
        for (int t = 0; t < 32; t++) {
            for (int u = prev + 1; u <= k[t]; u++) off[u] = base + t;
            prev = k[t];
        }
        if (base + 32 == n) {
            for (int u = prev + 1; u <= max_key; u++) off[u] = n;
        }
    } else {
        int prev = (base == 0) ? -1 : __ldg(keys + base - 1);
        for (int j = base; j < n; j++) {
            int cur = __ldg(keys + j);
            for (int u = prev + 1; u <= cur; u++) off[u] = j;
            prev = cur;
        }
        for (int u = prev + 1; u <= max_key; u++) off[u] = n;
    }
}

__global__ void __launch_bounds__(256) offsets_scatter_kernel(
    const int* __restrict__ buid, const int* __restrict__ ugid,
    int n_beh, int n_users, int num_groups)
{
    const int i = blockIdx.x * blockDim.x + threadIdx.x;
    const int n_beh_slots = (n_beh + 31) >> 5;

    if (i < n_beh_slots) {
        scatter32(buid, n_beh, g_u_off, n_users, i);
    } else {
        scatter32(ugid, n_users, g_g_off, num_groups, i - n_beh_slots);
    }
}

// ---------------------------------------------------------------------------
// Kernel 1: one warp per user (65536 independent warps -> perfect balance).
// Offsets precomputed. Unroll x4, 2 accumulators. Scratch stays L2-resident.
// This kernel runs at the LTS throughput cap (~13 TB/s of L2 gather traffic).
// ---------------------------------------------------------------------------
__global__ void __launch_bounds__(256) per_user_kernel(
    const int* __restrict__ user_ids,
    const int* __restrict__ bitem,
    const float* __restrict__ bcnt,
    const float* __restrict__ user_table,
    const float* __restrict__ item_table,
    int n_users)
{
    const int warp = (blockIdx.x * blockDim.x + threadIdx.x) >> 5;
    const int lane = threadIdx.x & 31;
    if (warp >= n_users) return;
    const int u   = warp;
    const int col = lane * 4;

    float4* dst = reinterpret_cast<float4*>(g_per_user + (size_t)u * EMB + col);

    const int uid = __ldg(user_ids + u);
    if (uid == 0) {
        *dst = make_float4(0.f, 0.f, 0.f, 0.f);
        return;
    }

    const int s = g_u_off[u];
    const int e = g_u_off[u + 1];

    float4 a0 = make_float4(0.f, 0.f, 0.f, 0.f);
    float4 a1 = make_float4(0.f, 0.f, 0.f, 0.f);

    int j = s;
    for (; j + 3 < e; j += 4) {
        int   i0 = __ldcs(bitem + j + 0);
        int   i1 = __ldcs(bitem + j + 1);
        int   i2 = __ldcs(bitem + j + 2);
        int   i3 = __ldcs(bitem + j + 3);
        float c0 = __ldcs(bcnt + j + 0);
        float c1 = __ldcs(bcnt + j + 1);
        float c2 = __ldcs(bcnt + j + 2);
        float c3 = __ldcs(bcnt + j + 3);
        float4 v0 = *reinterpret_cast<const float4*>(item_table + (size_t)i0 * EMB + col);
        float4 v1 = *reinterpret_cast<const float4*>(item_table + (size_t)i1 * EMB + col);
        float4 v2 = *reinterpret_cast<const float4*>(item_table + (size_t)i2 * EMB + col);
        float4 v3 = *reinterpret_cast<const float4*>(item_table + (size_t)i3 * EMB + col);
        a0.x += c0 * v0.x; a0.y += c0 * v0.y; a0.z += c0 * v0.z; a0.w += c0 * v0.w;
        a1.x += c1 * v1.x; a1.y += c1 * v1.y; a1.z += c1 * v1.z; a1.w += c1 * v1.w;
        a0.x += c2 * v2.x; a0.y += c2 * v2.y; a0.z += c2 * v2.z; a0.w += c2 * v2.w;
        a1.x += c3 * v3.x; a1.y += c3 * v3.y; a1.z += c3 * v3.z; a1.w += c3 * v3.w;
    }
    for (; j < e; j++) {
        int   i0 = __ldcs(bitem + j);
        float c0 = __ldcs(bcnt + j);
        float4 v0 = *reinterpret_cast<const float4*>(item_table + (size_t)i0 * EMB + col);
        a0.x += c0 * v0.x; a0.y += c0 * v0.y; a0.z += c0 * v0.z; a0.w += c0 * v0.w;
    }

    float4 ue = *reinterpret_cast<const float4*>(user_table + (size_t)uid * EMB + col);
    float4 outv;
    outv.x = (a0.x + a1.x) * ue.x;
    outv.y = (a0.y + a1.y) * ue.y;
    outv.z = (a0.z + a1.z) * ue.z;
    outv.w = (a0.w + a1.w) * ue.w;
    *dst = outv;
}

// ---------------------------------------------------------------------------
// Kernel 2: one 256-thread CTA per group. 32 lanes own float4 column slices,
// 8 user-partitions in parallel (stride 8), fixed-order smem combine.
// Scratch is L2-resident -> L2-bandwidth reads.
// ---------------------------------------------------------------------------
__global__ void __launch_bounds__(256) group_sum_kernel(
    float* __restrict__ out, int num_groups)
{
    const int g    = blockIdx.x;
    const int lane = threadIdx.x & 31;
    const int part = threadIdx.x >> 5;   // 0..7
    const int col  = lane * 4;

    __shared__ float4 s_part[8][32];

    const int s = g_g_off[g];
    const int e = g_g_off[g + 1];

    float4 acc = make_float4(0.f, 0.f, 0.f, 0.f);
    for (int u = s + part; u < e; u += 8) {
        float4 v = *reinterpret_cast<const float4*>(g_per_user + (size_t)u * EMB + col);
        acc.x += v.x; acc.y += v.y; acc.z += v.z; acc.w += v.w;
    }
    s_part[part][lane] = acc;
    __syncthreads();

    if (part == 0) {
        float4 r = make_float4(0.f, 0.f, 0.f, 0.f);
#pragma unroll
        for (int p = 0; p < 8; p++) {
            float4 v = s_part[p][lane];
            r.x += v.x; r.y += v.y; r.z += v.z; r.w += v.w;
        }
        *reinterpret_cast<float4*>(out + (size_t)g * EMB + col) = r;
    }
}

extern "C" void kernel_launch(void* const* d_in, const int* in_sizes, int n_in,
                              void* d_out, int out_size)
{
    const int*   user_ids   = (const int*)  d_in[0];
    const int*   ugid       = (const int*)  d_in[1];
    const int*   bitem      = (const int*)  d_in[2];
    const float* bcnt       = (const float*)d_in[3];
    const int*   buid       = (const int*)  d_in[4];
    const float* user_table = (const float*)d_in[5];
    const float* item_table = (const float*)d_in[6];

    const int n_users    = in_sizes[0];
    const int n_beh      = in_sizes[2];
    const int num_groups = out_size / EMB;

    float* out = (float*)d_out;

    {
        int slots = ((n_beh + 31) >> 5) + ((n_users + 31) >> 5);
        offsets_scatter_kernel<<<(slots + 255) / 256, 256>>>(
            buid, ugid, n_beh, n_users, num_groups);
    }

    {
        const int warps_per_block = 8;
        const int threads = warps_per_block * 32;
        const int blocks = (n_users + warps_per_block - 1) / warps_per_block;
        per_user_kernel<<<blocks, threads>>>(user_ids, bitem, bcnt,
                                             user_table, item_table, n_users);
    }

    group_sum_kernel<<<num_groups, 256>>>(out, num_groups);
}